// round 16
// baseline (speedup 1.0000x reference)
#include <cuda_runtime.h>
#include <cstdint>

#define PNUM 32
#define INF  7
#define D2   64
#define OUTF 4096           // floats per voxel
#define OBYTES (OUTF * 4)   // 16384 bytes per voxel
#define VPB  2

__global__ __launch_bounds__(128)
void vfe_kernel(const float* __restrict__ x,
                const float* __restrict__ W,
                const float* __restrict__ bias,
                float* __restrict__ out,
                int B)
{
    __shared__ float sx[VPB][PNUM * 8];              // staged x
    __shared__ float sglob[VPB][D2];                 // global vectors
    __shared__ __align__(16) float sbuf[VPB][OUTF];  // complete output tiles (32KB)

    const int t   = threadIdx.x;
    const int dg  = t & 15;              // dims [4*dg, 4*dg+4)
    const int pgr = t >> 4;              // points [4*pgr, 4*pgr+4)

    // Register-resident weights + bias.
    float w[4][INF], bb[4];
    #pragma unroll
    for (int k = 0; k < 4; k++) {
        const int d = dg * 4 + k;
        bb[k] = bias[d];
        #pragma unroll
        for (int i = 0; i < INF; i++) w[k][i] = W[d * INF + i];
    }

    const int v0   = blockIdx.x * VPB;
    const int nvox = min(VPB, B - v0);
    float* sxf = &sx[0][0];

    // Read burst: both voxels' x from (L2-resident) global.
    {
        const float* xv = x + (size_t)v0 * (PNUM * INF);
        const int lim = nvox * PNUM * INF;
        #pragma unroll
        for (int q = 0; q < 4; q++) {
            const int idx = t + q * 128;          // 0..511
            if (idx < lim) {
                const float val = __ldcg(xv + idx);
                const int r = idx / INF;
                sxf[r * 8 + (idx - r * INF)] = val;
            }
        }
    }
    __syncthreads();

    #pragma unroll 1
    for (int it = 0; it < nvox; it++) {
        const float* sxv = &sx[it][0];
        float* buf = &sbuf[it][0];

        // Phase 1: locals -> SMEM tile, half-row maxes -> sglob.
        #pragma unroll
        for (int j = 0; j < 4; j++) {
            const int p = pgr * 4 + j;
            const float4 a0 = *(const float4*)(sxv + p * 8);
            const float4 a1 = *(const float4*)(sxv + p * 8 + 4);

            float acc[4];
            #pragma unroll
            for (int k = 0; k < 4; k++) {
                float a = bb[k];
                a = fmaf(a0.x, w[k][0], a);
                a = fmaf(a0.y, w[k][1], a);
                a = fmaf(a0.z, w[k][2], a);
                a = fmaf(a0.w, w[k][3], a);
                a = fmaf(a1.x, w[k][4], a);
                a = fmaf(a1.y, w[k][5], a);
                a = fmaf(a1.z, w[k][6], a);
                acc[k] = a;
            }

            *(float4*)(buf + p * 128 + dg * 4) =
                make_float4(acc[0], acc[1], acc[2], acc[3]);

            float m = fmaxf(fmaxf(acc[0], acc[1]), fmaxf(acc[2], acc[3]));
            m = fmaxf(m, __shfl_xor_sync(0xffffffffu, m, 1));
            m = fmaxf(m, __shfl_xor_sync(0xffffffffu, m, 2));
            m = fmaxf(m, __shfl_xor_sync(0xffffffffu, m, 4));
            if ((t & 7) == 0)
                sglob[it][2 * p + ((t >> 3) & 1)] = m;
        }

        __syncthreads();   // publish sglob[it]

        // Phase 2: fill broadcast half of the SMEM tile.
        const float4 gv = *(const float4*)(&sglob[it][dg * 4]);
        #pragma unroll
        for (int j = 0; j < 4; j++) {
            const int p = pgr * 4 + j;
            *(float4*)(buf + p * 128 + 64 + dg * 4) = gv;
        }

        __syncthreads();   // tile complete, visible to all

        // One bulk TMA store: contiguous 16KB SMEM -> GMEM.
        if (t == 0) {
            asm volatile("fence.proxy.async.shared::cta;" ::: "memory");
            const uint32_t saddr = (uint32_t)__cvta_generic_to_shared(buf);
            float* gptr = out + (size_t)(v0 + it) * OUTF;
            asm volatile(
                "cp.async.bulk.global.shared::cta.bulk_group [%0], [%1], %2;"
                :: "l"(gptr), "r"(saddr), "r"(OBYTES) : "memory");
            asm volatile("cp.async.bulk.commit_group;" ::: "memory");
        }
        // No wait here: buffers are per-voxel, never reused within the block.
    }

    // Drain outstanding bulk stores before the CTA releases its SMEM.
    if (t == 0)
        asm volatile("cp.async.bulk.wait_group 0;" ::: "memory");
    __syncthreads();
}

extern "C" void kernel_launch(void* const* d_in, const int* in_sizes, int n_in,
                              void* d_out, int out_size)
{
    const float* x = (const float*)d_in[0];
    const float* W = (const float*)d_in[1];
    const float* b = (const float*)d_in[2];
    float* out     = (float*)d_out;

    const int B = in_sizes[0] / (PNUM * INF);       // 32768
    const int grid = (B + VPB - 1) / VPB;           // 16384
    vfe_kernel<<<grid, 128>>>(x, W, b, out, B);
}

// round 17
// speedup vs baseline: 1.0835x; 1.0835x over previous
#include <cuda_runtime.h>

#define PNUM 32
#define INF  7
#define D2   64
#define OUTF 4096   // 2*D2*PNUM floats per voxel
#define VPB  2      // voxels per block

__global__ __launch_bounds__(128, 8)
void vfe_kernel(const float* __restrict__ x,
                const float* __restrict__ W,
                const float* __restrict__ bias,
                float* __restrict__ out,
                int B)
{
    __shared__ float sx[VPB][PNUM * 8];  // staged x, rows padded to 8
    __shared__ float sglob[VPB][D2];     // per-voxel global vectors

    const int t   = threadIdx.x;
    const int dg  = t & 15;              // dims [4*dg, 4*dg+4)
    const int pgr = t >> 4;              // points [4*pgr, 4*pgr+4)

    // Register-resident weights + bias for this thread's 4 dims.
    float w[4][INF], bb[4];
    #pragma unroll
    for (int k = 0; k < 4; k++) {
        const int d = dg * 4 + k;
        bb[k] = bias[d];
        #pragma unroll
        for (int i = 0; i < INF; i++) w[k][i] = W[d * INF + i];
    }

    const int v0   = blockIdx.x * VPB;
    const int nvox = min(VPB, B - v0);
    float* sxf = &sx[0][0];

    // Read burst: both voxels' x (448 floats). __ldcg keeps x L2-resident
    // across graph replays; the evict-first write stream evicts around it.
    {
        const float* xv = x + (size_t)v0 * (PNUM * INF);
        const int lim = nvox * PNUM * INF;
        #pragma unroll
        for (int q = 0; q < 4; q++) {
            const int idx = t + q * 128;          // 0..511
            if (idx < lim) {
                const float val = __ldcg(xv + idx);
                const int r = idx / INF;
                sxf[r * 8 + (idx - r * INF)] = val;
            }
        }
    }
    __syncthreads();

    // ---- Phase 1: locals + maxes for BOTH voxels (no barrier between) ----
    #pragma unroll 1
    for (int it = 0; it < nvox; it++) {
        float* ov = out + (size_t)(v0 + it) * OUTF;
        const float* sxv = &sx[it][0];

        #pragma unroll
        for (int j = 0; j < 4; j++) {
            const int p = pgr * 4 + j;
            const float4 a0 = *(const float4*)(sxv + p * 8);
            const float4 a1 = *(const float4*)(sxv + p * 8 + 4);

            float acc[4];
            #pragma unroll
            for (int k = 0; k < 4; k++) {
                float a = bb[k];
                a = fmaf(a0.x, w[k][0], a);
                a = fmaf(a0.y, w[k][1], a);
                a = fmaf(a0.z, w[k][2], a);
                a = fmaf(a0.w, w[k][3], a);
                a = fmaf(a1.x, w[k][4], a);
                a = fmaf(a1.y, w[k][5], a);
                a = fmaf(a1.z, w[k][6], a);
                acc[k] = a;
            }

            // Local half of row p: coalesced streaming (evict-first) STG.128.
            __stcs((float4*)(ov + p * 128 + dg * 4),
                   make_float4(acc[0], acc[1], acc[2], acc[3]));

            // Half-row max over this 8-lane group.
            float m = fmaxf(fmaxf(acc[0], acc[1]), fmaxf(acc[2], acc[3]));
            m = fmaxf(m, __shfl_xor_sync(0xffffffffu, m, 1));
            m = fmaxf(m, __shfl_xor_sync(0xffffffffu, m, 2));
            m = fmaxf(m, __shfl_xor_sync(0xffffffffu, m, 4));
            if ((t & 7) == 0)
                sglob[it][2 * p + ((t >> 3) & 1)] = m;
        }
    }

    __syncthreads();   // the ONE publish barrier for both voxels

    // ---- Phase 2: pure broadcast-store burst for both voxels ----
    #pragma unroll 1
    for (int it = 0; it < nvox; it++) {
        float* ov = out + (size_t)(v0 + it) * OUTF;
        const float4 gv = *(const float4*)(&sglob[it][dg * 4]);
        #pragma unroll
        for (int j = 0; j < 4; j++) {
            const int p = pgr * 4 + j;
            __stcs((float4*)(ov + p * 128 + 64 + dg * 4), gv);
        }
    }
}

extern "C" void kernel_launch(void* const* d_in, const int* in_sizes, int n_in,
                              void* d_out, int out_size)
{
    const float* x = (const float*)d_in[0];
    const float* W = (const float*)d_in[1];
    const float* b = (const float*)d_in[2];
    float* out     = (float*)d_out;

    const int B = in_sizes[0] / (PNUM * INF);       // 32768
    const int grid = (B + VPB - 1) / VPB;           // 16384
    vfe_kernel<<<grid, 128>>>(x, W, b, out, B);
}